// round 9
// baseline (speedup 1.0000x reference)
#include <cuda_runtime.h>
#include <cstdint>

#define Mm 32768   // B*N points

// ---------------- static device scratch ----------------
__device__ float g_qg[Mm * 64];   // x @ (wq@g1)
__device__ float g_kg[Mm * 64];   // x @ (wk@g1)
__device__ float g_v [Mm * 64];   // x @ wv
__device__ float g_Wd2g1[4096];   // d2 @ g1
__device__ float g_Wqg1[4096];    // wq @ g1
__device__ float g_Wkg1[4096];    // wk @ g1
__device__ float g_cvec[64];      // d2b @ g1 + g1b

// ---------------- f32x2 packed-FMA helpers ----------------
__device__ __forceinline__ unsigned long long pack2(float x, float y) {
    unsigned long long r; asm("mov.b64 %0, {%1, %2};" : "=l"(r) : "f"(x), "f"(y)); return r;
}
__device__ __forceinline__ void fma2(unsigned long long& d, unsigned long long a, unsigned long long b) {
    asm("fma.rn.f32x2 %0, %1, %2, %0;" : "+l"(d) : "l"(a), "l"(b));
}
__device__ __forceinline__ float2 unpk(unsigned long long v) {
    float x, y; asm("mov.b64 {%0, %1}, %2;" : "=f"(x), "=f"(y) : "l"(v)); return make_float2(x, y);
}
__device__ __forceinline__ float foldp(unsigned long long v) {
    float2 u = unpk(v); return u.x + u.y;
}

// ---------------- 4x4-tile gemm (k0/k1) ----------------
__device__ __forceinline__ void rank1(float a0, float a1, float a2, float a3,
                                      ulonglong2 b, unsigned long long acc[4][2]) {
    unsigned long long t;
    t = pack2(a0, a0); fma2(acc[0][0], t, b.x); fma2(acc[0][1], t, b.y);
    t = pack2(a1, a1); fma2(acc[1][0], t, b.x); fma2(acc[1][1], t, b.y);
    t = pack2(a2, a2); fma2(acc[2][0], t, b.x); fma2(acc[2][1], t, b.y);
    t = pack2(a3, a3); fma2(acc[3][0], t, b.x); fma2(acc[3][1], t, b.y);
}
__device__ __forceinline__ void gemm64(const float* As, const float* Ws,
                                       int r0, int c0, unsigned long long acc[4][2]) {
#pragma unroll
    for (int i = 0; i < 4; i++) { acc[i][0] = 0ULL; acc[i][1] = 0ULL; }
#pragma unroll
    for (int k4 = 0; k4 < 16; ++k4) {
        float4 a0 = *reinterpret_cast<const float4*>(As + (r0 + 0) * 68 + k4 * 4);
        float4 a1 = *reinterpret_cast<const float4*>(As + (r0 + 1) * 68 + k4 * 4);
        float4 a2 = *reinterpret_cast<const float4*>(As + (r0 + 2) * 68 + k4 * 4);
        float4 a3 = *reinterpret_cast<const float4*>(As + (r0 + 3) * 68 + k4 * 4);
        ulonglong2 b0 = *reinterpret_cast<const ulonglong2*>(Ws + (k4 * 4 + 0) * 68 + c0);
        ulonglong2 b1 = *reinterpret_cast<const ulonglong2*>(Ws + (k4 * 4 + 1) * 68 + c0);
        ulonglong2 b2 = *reinterpret_cast<const ulonglong2*>(Ws + (k4 * 4 + 2) * 68 + c0);
        ulonglong2 b3 = *reinterpret_cast<const ulonglong2*>(Ws + (k4 * 4 + 3) * 68 + c0);
        rank1(a0.x, a1.x, a2.x, a3.x, b0, acc);
        rank1(a0.y, a1.y, a2.y, a3.y, b1, acc);
        rank1(a0.z, a1.z, a2.z, a3.z, b2, acc);
        rank1(a0.w, a1.w, a2.w, a3.w, b3, acc);
    }
}
__device__ __forceinline__ void loadW(float* dst, const float* __restrict__ src, int tid) {
#pragma unroll
    for (int e = tid; e < 1024; e += 256) {
        int row = e >> 4, c4 = e & 15;
        float4 v = *reinterpret_cast<const float4*>(src + row * 64 + c4 * 4);
        *reinterpret_cast<float4*>(dst + row * 68 + c4 * 4) = v;
    }
}

// =========================================================================
// k0: weight products (canary kernel — keep identical across rounds)
// =========================================================================
__global__ __launch_bounds__(256)
void k0_prep(const float* __restrict__ d2w, const float* __restrict__ g1w,
             const float* __restrict__ wq, const float* __restrict__ wk,
             const float* __restrict__ d2b, const float* __restrict__ g1b) {
    __shared__ float As[64 * 68];
    __shared__ float Bs[64 * 68];
    const int tid = threadIdx.x, m = blockIdx.x;
    const float* A = (m == 0) ? d2w : (m == 1) ? wq : wk;
    loadW(As, A, tid);
    loadW(Bs, g1w, tid);
    __syncthreads();
    const int r0 = (tid >> 4) * 4, c0 = (tid & 15) * 4;
    unsigned long long acc[4][2];
    gemm64(As, Bs, r0, c0, acc);
    float* dst = (m == 0) ? g_Wd2g1 : (m == 1) ? g_Wqg1 : g_Wkg1;
#pragma unroll
    for (int i = 0; i < 4; i++) {
        float2 u0 = unpk(acc[i][0]), u1 = unpk(acc[i][1]);
        *reinterpret_cast<float4*>(dst + (r0 + i) * 64 + c0) = make_float4(u0.x, u0.y, u1.x, u1.y);
    }
    if (m == 0 && tid < 64) {
        float c = g1b[tid];
#pragma unroll 8
        for (int k = 0; k < 64; k++) c = fmaf(__ldg(&d2b[k]), Bs[k * 68 + tid], c);
        g_cvec[tid] = c;
    }
}

// =========================================================================
// k1: x = features@fc1+b ; qg = x@Wqg1 ; kg = x@Wkg1 ; v = x@wv
// =========================================================================
__global__ __launch_bounds__(256)
void k1_proj(const float* __restrict__ features,
             const float* __restrict__ fc1w, const float* __restrict__ fc1b,
             const float* __restrict__ wv) {
    __shared__ float Fs[64 * 68];
    __shared__ float Ws[64 * 68];
    const int tid = threadIdx.x;
    const int m0 = blockIdx.x * 64;
    const int r0 = (tid >> 4) * 4, c0 = (tid & 15) * 4;

#pragma unroll
    for (int e = tid; e < 1024; e += 256) {
        int row = e >> 4, c4 = e & 15;
        float4 v = *reinterpret_cast<const float4*>(features + (m0 + row) * 64 + c4 * 4);
        *reinterpret_cast<float4*>(Fs + row * 68 + c4 * 4) = v;
    }
    loadW(Ws, fc1w, tid);
    __syncthreads();

    unsigned long long acc[4][2];
    gemm64(Fs, Ws, r0, c0, acc);
    __syncthreads();
#pragma unroll
    for (int i = 0; i < 4; i++) {
        float2 u0 = unpk(acc[i][0]), u1 = unpk(acc[i][1]);
        Fs[(r0 + i) * 68 + c0 + 0] = u0.x + __ldg(&fc1b[c0 + 0]);
        Fs[(r0 + i) * 68 + c0 + 1] = u0.y + __ldg(&fc1b[c0 + 1]);
        Fs[(r0 + i) * 68 + c0 + 2] = u1.x + __ldg(&fc1b[c0 + 2]);
        Fs[(r0 + i) * 68 + c0 + 3] = u1.y + __ldg(&fc1b[c0 + 3]);
    }
    loadW(Ws, (const float*)g_Wqg1, tid);
    __syncthreads();
    gemm64(Fs, Ws, r0, c0, acc);
#pragma unroll
    for (int i = 0; i < 4; i++) {
        float2 u0 = unpk(acc[i][0]), u1 = unpk(acc[i][1]);
        *reinterpret_cast<float4*>(g_qg + (m0 + r0 + i) * 64 + c0) = make_float4(u0.x, u0.y, u1.x, u1.y);
    }
    __syncthreads();
    loadW(Ws, (const float*)g_Wkg1, tid);
    __syncthreads();
    gemm64(Fs, Ws, r0, c0, acc);
#pragma unroll
    for (int i = 0; i < 4; i++) {
        float2 u0 = unpk(acc[i][0]), u1 = unpk(acc[i][1]);
        *reinterpret_cast<float4*>(g_kg + (m0 + r0 + i) * 64 + c0) = make_float4(u0.x, u0.y, u1.x, u1.y);
    }
    __syncthreads();
    loadW(Ws, wv, tid);
    __syncthreads();
    gemm64(Fs, Ws, r0, c0, acc);
#pragma unroll
    for (int i = 0; i < 4; i++) {
        float2 u0 = unpk(acc[i][0]), u1 = unpk(acc[i][1]);
        *reinterpret_cast<float4*>(g_v + (m0 + r0 + i) * 64 + c0) = make_float4(u0.x, u0.y, u1.x, u1.y);
    }
}

// =========================================================================
// k2: 128 thr = 2 groups x 64 thr; group = 64 rows (4 pts x 16 nbrs).
// K-paired f32x2 GEMM: acc.lo/.hi accumulate even/odd k; fold at epilogue.
// Tb/vpS stride 68 (float4-safe, 8B reads conflict-free: 2r mod 32 distinct).
// Wt transposed col-major stride 66 + 2*(c>>3) pad (8B/scalar only).
// =========================================================================
__device__ __forceinline__ void gemmT2(const float* __restrict__ Tb,
                                       const float* __restrict__ Wt,
                                       int tr, int tc, unsigned long long acc[8][8]) {
    const unsigned long long* a0 = reinterpret_cast<const unsigned long long*>(Tb + (tr +  0) * 68);
    const unsigned long long* a1 = reinterpret_cast<const unsigned long long*>(Tb + (tr +  8) * 68);
    const unsigned long long* a2 = reinterpret_cast<const unsigned long long*>(Tb + (tr + 16) * 68);
    const unsigned long long* a3 = reinterpret_cast<const unsigned long long*>(Tb + (tr + 24) * 68);
    const unsigned long long* a4 = reinterpret_cast<const unsigned long long*>(Tb + (tr + 32) * 68);
    const unsigned long long* a5 = reinterpret_cast<const unsigned long long*>(Tb + (tr + 40) * 68);
    const unsigned long long* a6 = reinterpret_cast<const unsigned long long*>(Tb + (tr + 48) * 68);
    const unsigned long long* a7 = reinterpret_cast<const unsigned long long*>(Tb + (tr + 56) * 68);
    // col c (global 8*tc + c): word offset (8*tc+c)*66 + 2*tc
    const unsigned long long* wbase = reinterpret_cast<const unsigned long long*>(Wt + tc * 530);
#pragma unroll
    for (int i = 0; i < 8; i++)
#pragma unroll
        for (int c = 0; c < 8; c++) acc[i][c] = 0ULL;
#pragma unroll
    for (int kp = 0; kp < 32; kp++) {
        unsigned long long av[8], wv[8];
        av[0] = a0[kp]; av[1] = a1[kp]; av[2] = a2[kp]; av[3] = a3[kp];
        av[4] = a4[kp]; av[5] = a5[kp]; av[6] = a6[kp]; av[7] = a7[kp];
#pragma unroll
        for (int c = 0; c < 8; c++) wv[c] = wbase[c * 33 + kp];
#pragma unroll
        for (int i = 0; i < 8; i++)
#pragma unroll
            for (int c = 0; c < 8; c++)
                fma2(acc[i][c], av[i], wv[c]);
    }
}

// stage W transposed: dst[c*66 + 2*(c>>3) + k] = src[k*64 + c]
__device__ __forceinline__ void loadWtT(float* dst, const float* __restrict__ src, int tid) {
#pragma unroll
    for (int e = tid; e < 1024; e += 128) {
        int k = e >> 4, c4 = e & 15;
        float4 v = __ldg(reinterpret_cast<const float4*>(src + k * 64 + c4 * 4));
        int c = c4 * 4;
        int base = c * 66 + 2 * (c >> 3) + k;
        dst[base]       = v.x;
        dst[base + 66]  = v.y;
        dst[base + 132] = v.z;
        dst[base + 198] = v.w;
    }
}

__global__ __launch_bounds__(128)
void k2_main(const float* __restrict__ xyz, const float* __restrict__ features,
             const int* __restrict__ knn,
             const float* __restrict__ d1w, const float* __restrict__ d1b,
             const float* __restrict__ d2w, const float* __restrict__ d2b,
             const float* __restrict__ g2w, const float* __restrict__ g2b,
             const float* __restrict__ fc2w, const float* __restrict__ fc2b,
             float* __restrict__ outRes, float* __restrict__ outAttn) {
    extern __shared__ float sm[];
    float* Wt   = sm;                       // 4240 (transposed + padded)
    const int tid = threadIdx.x;
    const int g = tid >> 6, l = tid & 63;
    const int tc = l & 7, tr = l >> 3;
    float* Tb   = sm + 4240  + g * 4352;    // 64 x stride 68
    float* vpS  = sm + 12944 + g * 4352;    // 64 x stride 68
    float* qgS  = sm + 21648;               // 512
    float* resS = sm + 22160;               // 512
    int* growsS = (int*)(sm + 22672);       // 128
    float* d1S  = sm + 22800;               // 192
    float* d1bS = sm + 22992;
    float* d2bS = sm + 23056;
    float* cvecS= sm + 23120;
    float* g2bS = sm + 23184;               // end 23248 floats = 92992 B
    const int pbase = blockIdx.x * 8;

    // ---- setup ----
    loadWtT(Wt, d2w, tid);
    for (int e = tid; e < 192; e += 128) d1S[e] = d1w[e];
    if (tid < 64) { d1bS[tid] = d1b[tid]; d2bS[tid] = d2b[tid]; cvecS[tid] = g_cvec[tid]; g2bS[tid] = g2b[tid]; }
    for (int e = tid; e < 512; e += 128) qgS[e] = g_qg[(pbase + (e >> 6)) * 64 + (e & 63)];

    const int pi_st = pbase + g * 4 + (l >> 4);
    const int grow_st = ((pi_st >> 13) << 13) | knn[pi_st * 16 + (l & 15)];
    growsS[tid] = grow_st;
    const float rx = xyz[pi_st * 3 + 0] - xyz[grow_st * 3 + 0];
    const float ry = xyz[pi_st * 3 + 1] - xyz[grow_st * 3 + 1];
    const float rz = xyz[pi_st * 3 + 2] - xyz[grow_st * 3 + 2];
    __syncthreads();

    // ---- stage T = relu(rel@d1 + d1b) ----
    {
        const int r = l;
#pragma unroll
        for (int c4 = 0; c4 < 16; c4++) {
            float v[4];
#pragma unroll
            for (int u = 0; u < 4; u++) {
                int f = c4 * 4 + u;
                v[u] = fmaxf(fmaf(rx, d1S[f], fmaf(ry, d1S[64 + f], fmaf(rz, d1S[128 + f], d1bS[f]))), 0.f);
            }
            *reinterpret_cast<float4*>(Tb + r * 68 + c4 * 4) = make_float4(v[0], v[1], v[2], v[3]);
        }
    }
    __syncthreads();

    const int c0 = tc * 8;
    unsigned long long acc[8][8];

    // ---- GEMM1: pos = T@d2 (+d2b); vp = v_gather + pos -> vpS ----
    gemmT2(Tb, Wt, tr, tc, acc);
#pragma unroll
    for (int i = 0; i < 8; i++) {
        int r = tr + 8 * i;
        int grow = growsS[g * 64 + r];
        float4 v0 = __ldg(reinterpret_cast<const float4*>(g_v + (size_t)grow * 64 + c0));
        float4 v1 = __ldg(reinterpret_cast<const float4*>(g_v + (size_t)grow * 64 + c0 + 4));
        float4 w0 = make_float4(v0.x + foldp(acc[i][0]) + d2bS[c0 + 0],
                                v0.y + foldp(acc[i][1]) + d2bS[c0 + 1],
                                v0.z + foldp(acc[i][2]) + d2bS[c0 + 2],
                                v0.w + foldp(acc[i][3]) + d2bS[c0 + 3]);
        float4 w1 = make_float4(v1.x + foldp(acc[i][4]) + d2bS[c0 + 4],
                                v1.y + foldp(acc[i][5]) + d2bS[c0 + 5],
                                v1.z + foldp(acc[i][6]) + d2bS[c0 + 6],
                                v1.w + foldp(acc[i][7]) + d2bS[c0 + 7]);
        *reinterpret_cast<float4*>(vpS + r * 68 + c0)     = w0;
        *reinterpret_cast<float4*>(vpS + r * 68 + c0 + 4) = w1;
    }
    __syncthreads();                 // GEMM1 Wt reads done
    loadWtT(Wt, (const float*)g_Wd2g1, tid);
    __syncthreads();

    // ---- GEMM2: Tg = T@(d2@g1); a1 = relu(Tg + qg - kg + cvec) ----
    gemmT2(Tb, Wt, tr, tc, acc);
    float a1s[8][8];
#pragma unroll
    for (int i = 0; i < 8; i++) {
        int r = tr + 8 * i;
        int grow = growsS[g * 64 + r];
        int lp = g * 4 + (r >> 4);
        float4 k0v = __ldg(reinterpret_cast<const float4*>(g_kg + (size_t)grow * 64 + c0));
        float4 k1v = __ldg(reinterpret_cast<const float4*>(g_kg + (size_t)grow * 64 + c0 + 4));
        float4 q0 = *reinterpret_cast<const float4*>(qgS + lp * 64 + c0);
        float4 q1 = *reinterpret_cast<const float4*>(qgS + lp * 64 + c0 + 4);
        a1s[i][0] = fmaxf(foldp(acc[i][0]) + q0.x - k0v.x + cvecS[c0 + 0], 0.f);
        a1s[i][1] = fmaxf(foldp(acc[i][1]) + q0.y - k0v.y + cvecS[c0 + 1], 0.f);
        a1s[i][2] = fmaxf(foldp(acc[i][2]) + q0.z - k0v.z + cvecS[c0 + 2], 0.f);
        a1s[i][3] = fmaxf(foldp(acc[i][3]) + q0.w - k0v.w + cvecS[c0 + 3], 0.f);
        a1s[i][4] = fmaxf(foldp(acc[i][4]) + q1.x - k1v.x + cvecS[c0 + 4], 0.f);
        a1s[i][5] = fmaxf(foldp(acc[i][5]) + q1.y - k1v.y + cvecS[c0 + 5], 0.f);
        a1s[i][6] = fmaxf(foldp(acc[i][6]) + q1.z - k1v.z + cvecS[c0 + 6], 0.f);
        a1s[i][7] = fmaxf(foldp(acc[i][7]) + q1.w - k1v.w + cvecS[c0 + 7], 0.f);
    }
    __syncthreads();                 // GEMM2 Tb/Wt reads done
#pragma unroll
    for (int i = 0; i < 8; i++) {
        int r = tr + 8 * i;
        *reinterpret_cast<float4*>(Tb + r * 68 + c0)     = make_float4(a1s[i][0], a1s[i][1], a1s[i][2], a1s[i][3]);
        *reinterpret_cast<float4*>(Tb + r * 68 + c0 + 4) = make_float4(a1s[i][4], a1s[i][5], a1s[i][6], a1s[i][7]);
    }
    loadWtT(Wt, g2w, tid);
    __syncthreads();

    // ---- GEMM3: logits = a1@g2 + g2b ----
    gemmT2(Tb, Wt, tr, tc, acc);
#pragma unroll
    for (int i = 0; i < 8; i++)
#pragma unroll
        for (int c = 0; c < 8; c++)
            a1s[i][c] = foldp(acc[i][c]) + g2bS[c0 + c];
    __syncthreads();                 // GEMM3 reads done
#pragma unroll
    for (int i = 0; i < 8; i++) {
        int r = tr + 8 * i;
        *reinterpret_cast<float4*>(Tb + r * 68 + c0)     = make_float4(a1s[i][0], a1s[i][1], a1s[i][2], a1s[i][3]);
        *reinterpret_cast<float4*>(Tb + r * 68 + c0 + 4) = make_float4(a1s[i][4], a1s[i][5], a1s[i][6], a1s[i][7]);
    }
    __syncthreads();

    // ---- softmax over neighbors (axis j) per (point, channel) + res ----
    {
        const int f = l;
#pragma unroll
        for (int p = 0; p < 4; p++) {
            const int pi = pbase + g * 4 + p;
            float z[16], m = -3.402823e38f;
#pragma unroll
            for (int j = 0; j < 16; j++) {
                z[j] = Tb[(p * 16 + j) * 68 + f];
                m = fmaxf(m, z[j]);
            }
            float s = 0.f;
#pragma unroll
            for (int j = 0; j < 16; j++) { float e = __expf((z[j] - m) * 0.125f); z[j] = e; s += e; }
            float inv = 1.f / s, racc = 0.f;
#pragma unroll
            for (int j = 0; j < 16; j++) {
                float a = z[j] * inv;
                outAttn[((size_t)pi * 16 + j) * 64 + f] = a;
                racc = fmaf(a, vpS[(p * 16 + j) * 68 + f], racc);
            }
            resS[(g * 4 + p) * 64 + f] = racc;
        }
    }
    __syncthreads();

    // ---- out = res@fc2 + fc2b + features ----
    {
        const int f = l, lpb = g * 4;
        float o0 = fc2b[f] + features[(size_t)(pbase + lpb + 0) * 64 + f];
        float o1 = fc2b[f] + features[(size_t)(pbase + lpb + 1) * 64 + f];
        float o2 = fc2b[f] + features[(size_t)(pbase + lpb + 2) * 64 + f];
        float o3 = fc2b[f] + features[(size_t)(pbase + lpb + 3) * 64 + f];
#pragma unroll 8
        for (int i = 0; i < 64; i++) {
            float w = __ldg(fc2w + i * 64 + f);
            o0 = fmaf(resS[(lpb + 0) * 64 + i], w, o0);
            o1 = fmaf(resS[(lpb + 1) * 64 + i], w, o1);
            o2 = fmaf(resS[(lpb + 2) * 64 + i], w, o2);
            o3 = fmaf(resS[(lpb + 3) * 64 + i], w, o3);
        }
        outRes[(size_t)(pbase + lpb + 0) * 64 + f] = o0;
        outRes[(size_t)(pbase + lpb + 1) * 64 + f] = o1;
        outRes[(size_t)(pbase + lpb + 2) * 64 + f] = o2;
        outRes[(size_t)(pbase + lpb + 3) * 64 + f] = o3;
    }
}

// =========================================================================
extern "C" void kernel_launch(void* const* d_in, const int* in_sizes, int n_in,
                              void* d_out, int out_size) {
    const float* xyz      = (const float*)d_in[0];
    const float* features = (const float*)d_in[1];
    const int*   knn      = (const int*)d_in[2];
    const float* fc1w = (const float*)d_in[3];
    const float* fc1b = (const float*)d_in[4];
    const float* fc2w = (const float*)d_in[5];
    const float* fc2b = (const float*)d_in[6];
    const float* d1w  = (const float*)d_in[7];
    const float* d1b  = (const float*)d_in[8];
    const float* d2w  = (const float*)d_in[9];
    const float* d2b  = (const float*)d_in[10];
    const float* g1w  = (const float*)d_in[11];
    const float* g1b  = (const float*)d_in[12];
    const float* g2w  = (const float*)d_in[13];
    const float* g2b  = (const float*)d_in[14];
    const float* wq   = (const float*)d_in[15];
    const float* wk   = (const float*)d_in[16];
    const float* wv   = (const float*)d_in[17];

    float* outRes  = (float*)d_out;
    float* outAttn = outRes + (size_t)Mm * 64;   // tuple order: (res, attn)

    const int smem2 = 23248 * 4;   // 92992 B -> 2 CTAs/SM
    cudaFuncSetAttribute(k2_main, cudaFuncAttributeMaxDynamicSharedMemorySize, smem2);

    k0_prep<<<3, 256>>>(d2w, g1w, wq, wk, d2b, g1b);
    k1_proj<<<Mm / 64, 256>>>(features, fc1w, fc1b, wv);
    k2_main<<<Mm / 8, 128, smem2>>>(xyz, features, knn,
                                    d1w, d1b, d2w, d2b, g2w, g2b,
                                    fc2w, fc2b, outRes, outAttn);
}

// round 10
// speedup vs baseline: 1.3872x; 1.3872x over previous
#include <cuda_runtime.h>
#include <cstdint>

#define Mm 32768   // B*N points

// ---------------- static device scratch ----------------
__device__ float g_qg[Mm * 64];   // x @ (wq@g1)
__device__ float g_kg[Mm * 64];   // x @ (wk@g1)
__device__ float g_v [Mm * 64];   // x @ wv
__device__ float g_Wd2g1[4096];   // d2 @ g1
__device__ float g_Wqg1[4096];    // wq @ g1
__device__ float g_Wkg1[4096];    // wk @ g1
__device__ float g_cvec[64];      // d2b @ g1 + g1b

// ---------------- f32x2 packed-FMA helpers ----------------
__device__ __forceinline__ unsigned long long pack2(float x, float y) {
    unsigned long long r; asm("mov.b64 %0, {%1, %2};" : "=l"(r) : "f"(x), "f"(y)); return r;
}
__device__ __forceinline__ void fma2(unsigned long long& d, unsigned long long a, unsigned long long b) {
    asm("fma.rn.f32x2 %0, %1, %2, %0;" : "+l"(d) : "l"(a), "l"(b));
}
__device__ __forceinline__ float2 unpk(unsigned long long v) {
    float x, y; asm("mov.b64 {%0, %1}, %2;" : "=f"(x), "=f"(y) : "l"(v)); return make_float2(x, y);
}

// ---------------- 4x4-tile gemm (k0/k1) ----------------
__device__ __forceinline__ void rank1(float a0, float a1, float a2, float a3,
                                      ulonglong2 b, unsigned long long acc[4][2]) {
    unsigned long long t;
    t = pack2(a0, a0); fma2(acc[0][0], t, b.x); fma2(acc[0][1], t, b.y);
    t = pack2(a1, a1); fma2(acc[1][0], t, b.x); fma2(acc[1][1], t, b.y);
    t = pack2(a2, a2); fma2(acc[2][0], t, b.x); fma2(acc[2][1], t, b.y);
    t = pack2(a3, a3); fma2(acc[3][0], t, b.x); fma2(acc[3][1], t, b.y);
}
__device__ __forceinline__ void gemm64(const float* As, const float* Ws,
                                       int r0, int c0, unsigned long long acc[4][2]) {
#pragma unroll
    for (int i = 0; i < 4; i++) { acc[i][0] = 0ULL; acc[i][1] = 0ULL; }
#pragma unroll
    for (int k4 = 0; k4 < 16; ++k4) {
        float4 a0 = *reinterpret_cast<const float4*>(As + (r0 + 0) * 68 + k4 * 4);
        float4 a1 = *reinterpret_cast<const float4*>(As + (r0 + 1) * 68 + k4 * 4);
        float4 a2 = *reinterpret_cast<const float4*>(As + (r0 + 2) * 68 + k4 * 4);
        float4 a3 = *reinterpret_cast<const float4*>(As + (r0 + 3) * 68 + k4 * 4);
        ulonglong2 b0 = *reinterpret_cast<const ulonglong2*>(Ws + (k4 * 4 + 0) * 68 + c0);
        ulonglong2 b1 = *reinterpret_cast<const ulonglong2*>(Ws + (k4 * 4 + 1) * 68 + c0);
        ulonglong2 b2 = *reinterpret_cast<const ulonglong2*>(Ws + (k4 * 4 + 2) * 68 + c0);
        ulonglong2 b3 = *reinterpret_cast<const ulonglong2*>(Ws + (k4 * 4 + 3) * 68 + c0);
        rank1(a0.x, a1.x, a2.x, a3.x, b0, acc);
        rank1(a0.y, a1.y, a2.y, a3.y, b1, acc);
        rank1(a0.z, a1.z, a2.z, a3.z, b2, acc);
        rank1(a0.w, a1.w, a2.w, a3.w, b3, acc);
    }
}
__device__ __forceinline__ void loadW(float* dst, const float* __restrict__ src, int tid) {
#pragma unroll
    for (int e = tid; e < 1024; e += 256) {
        int row = e >> 4, c4 = e & 15;
        float4 v = *reinterpret_cast<const float4*>(src + row * 64 + c4 * 4);
        *reinterpret_cast<float4*>(dst + row * 68 + c4 * 4) = v;
    }
}

// =========================================================================
// k0: weight products (canary kernel — keep identical across rounds)
// =========================================================================
__global__ __launch_bounds__(256)
void k0_prep(const float* __restrict__ d2w, const float* __restrict__ g1w,
             const float* __restrict__ wq, const float* __restrict__ wk,
             const float* __restrict__ d2b, const float* __restrict__ g1b) {
    __shared__ float As[64 * 68];
    __shared__ float Bs[64 * 68];
    const int tid = threadIdx.x, m = blockIdx.x;
    const float* A = (m == 0) ? d2w : (m == 1) ? wq : wk;
    loadW(As, A, tid);
    loadW(Bs, g1w, tid);
    __syncthreads();
    const int r0 = (tid >> 4) * 4, c0 = (tid & 15) * 4;
    unsigned long long acc[4][2];
    gemm64(As, Bs, r0, c0, acc);
    float* dst = (m == 0) ? g_Wd2g1 : (m == 1) ? g_Wqg1 : g_Wkg1;
#pragma unroll
    for (int i = 0; i < 4; i++) {
        float2 u0 = unpk(acc[i][0]), u1 = unpk(acc[i][1]);
        *reinterpret_cast<float4*>(dst + (r0 + i) * 64 + c0) = make_float4(u0.x, u0.y, u1.x, u1.y);
    }
    if (m == 0 && tid < 64) {
        float c = g1b[tid];
#pragma unroll 8
        for (int k = 0; k < 64; k++) c = fmaf(__ldg(&d2b[k]), Bs[k * 68 + tid], c);
        g_cvec[tid] = c;
    }
}

// =========================================================================
// k1: x = features@fc1+b ; qg = x@Wqg1 ; kg = x@Wkg1 ; v = x@wv
// =========================================================================
__global__ __launch_bounds__(256)
void k1_proj(const float* __restrict__ features,
             const float* __restrict__ fc1w, const float* __restrict__ fc1b,
             const float* __restrict__ wv) {
    __shared__ float Fs[64 * 68];
    __shared__ float Ws[64 * 68];
    const int tid = threadIdx.x;
    const int m0 = blockIdx.x * 64;
    const int r0 = (tid >> 4) * 4, c0 = (tid & 15) * 4;

#pragma unroll
    for (int e = tid; e < 1024; e += 256) {
        int row = e >> 4, c4 = e & 15;
        float4 v = *reinterpret_cast<const float4*>(features + (m0 + row) * 64 + c4 * 4);
        *reinterpret_cast<float4*>(Fs + row * 68 + c4 * 4) = v;
    }
    loadW(Ws, fc1w, tid);
    __syncthreads();

    unsigned long long acc[4][2];
    gemm64(Fs, Ws, r0, c0, acc);
    __syncthreads();
#pragma unroll
    for (int i = 0; i < 4; i++) {
        float2 u0 = unpk(acc[i][0]), u1 = unpk(acc[i][1]);
        Fs[(r0 + i) * 68 + c0 + 0] = u0.x + __ldg(&fc1b[c0 + 0]);
        Fs[(r0 + i) * 68 + c0 + 1] = u0.y + __ldg(&fc1b[c0 + 1]);
        Fs[(r0 + i) * 68 + c0 + 2] = u1.x + __ldg(&fc1b[c0 + 2]);
        Fs[(r0 + i) * 68 + c0 + 3] = u1.y + __ldg(&fc1b[c0 + 3]);
    }
    loadW(Ws, (const float*)g_Wqg1, tid);
    __syncthreads();
    gemm64(Fs, Ws, r0, c0, acc);
#pragma unroll
    for (int i = 0; i < 4; i++) {
        float2 u0 = unpk(acc[i][0]), u1 = unpk(acc[i][1]);
        *reinterpret_cast<float4*>(g_qg + (m0 + r0 + i) * 64 + c0) = make_float4(u0.x, u0.y, u1.x, u1.y);
    }
    __syncthreads();
    loadW(Ws, (const float*)g_Wkg1, tid);
    __syncthreads();
    gemm64(Fs, Ws, r0, c0, acc);
#pragma unroll
    for (int i = 0; i < 4; i++) {
        float2 u0 = unpk(acc[i][0]), u1 = unpk(acc[i][1]);
        *reinterpret_cast<float4*>(g_kg + (m0 + r0 + i) * 64 + c0) = make_float4(u0.x, u0.y, u1.x, u1.y);
    }
    __syncthreads();
    loadW(Ws, wv, tid);
    __syncthreads();
    gemm64(Fs, Ws, r0, c0, acc);
#pragma unroll
    for (int i = 0; i < 4; i++) {
        float2 u0 = unpk(acc[i][0]), u1 = unpk(acc[i][1]);
        *reinterpret_cast<float4*>(g_v + (m0 + r0 + i) * 64 + c0) = make_float4(u0.x, u0.y, u1.x, u1.y);
    }
}

// =========================================================================
// k2: 256 thr = 2 groups x 128 thr; group = 64 rows (4 pts x 16 nbrs).
// 4x8 register tiles (16 row-tiles x 8 col-tiles) -> 16 warps/SM at
// 2 CTAs/SM: 4 warps/SMSP keep the fma pipe saturated through stalls.
// Same smem layout / gemm structure as the proven R7 kernel.
// =========================================================================
__device__ __forceinline__ void gemmT4(const float* __restrict__ Tb,
                                       const float* __restrict__ W,
                                       int trr, int tcoff, unsigned long long acc[4][4]) {
    const float4* ap0 = reinterpret_cast<const float4*>(Tb + (trr +  0) * 68);
    const float4* ap1 = reinterpret_cast<const float4*>(Tb + (trr + 16) * 68);
    const float4* ap2 = reinterpret_cast<const float4*>(Tb + (trr + 32) * 68);
    const float4* ap3 = reinterpret_cast<const float4*>(Tb + (trr + 48) * 68);
    const ulonglong2* wp = reinterpret_cast<const ulonglong2*>(W + tcoff);
#pragma unroll
    for (int i = 0; i < 4; i++) { acc[i][0] = acc[i][1] = acc[i][2] = acc[i][3] = 0ULL; }
#pragma unroll
    for (int k4 = 0; k4 < 16; k4++) {
        float4 Av[4];
        Av[0] = ap0[k4]; Av[1] = ap1[k4]; Av[2] = ap2[k4]; Av[3] = ap3[k4];
#pragma unroll
        for (int kk = 0; kk < 4; kk++) {
            ulonglong2 b0 = wp[(k4 * 4 + kk) * 17];
            ulonglong2 b1 = wp[(k4 * 4 + kk) * 17 + 1];
#pragma unroll
            for (int i = 0; i < 4; i++) {
                float a = (kk == 0) ? Av[i].x : (kk == 1) ? Av[i].y : (kk == 2) ? Av[i].z : Av[i].w;
                unsigned long long t = pack2(a, a);
                fma2(acc[i][0], t, b0.x); fma2(acc[i][1], t, b0.y);
                fma2(acc[i][2], t, b1.x); fma2(acc[i][3], t, b1.y);
            }
        }
    }
}

// cooperative padded weight load (256 threads): col -> col + 4*(col>=32)
__device__ __forceinline__ void loadWp(float* dst, const float* __restrict__ src, int tid) {
#pragma unroll
    for (int e = tid; e < 1024; e += 256) {
        int row = e >> 4, c4 = e & 15;
        float4 v = __ldg(reinterpret_cast<const float4*>(src + row * 64 + c4 * 4));
        *reinterpret_cast<float4*>(dst + row * 68 + c4 * 4 + ((c4 >> 3) << 2)) = v;
    }
}

__global__ __launch_bounds__(256, 2)
void k2_main(const float* __restrict__ xyz, const float* __restrict__ features,
             const int* __restrict__ knn,
             const float* __restrict__ d1w, const float* __restrict__ d1b,
             const float* __restrict__ d2w, const float* __restrict__ d2b,
             const float* __restrict__ g2w, const float* __restrict__ g2b,
             const float* __restrict__ fc2w, const float* __restrict__ fc2b,
             float* __restrict__ outRes, float* __restrict__ outAttn) {
    extern __shared__ float sm[];
    float* Wbuf  = sm;                     // 4352 (padded cols)
    const int tid = threadIdx.x;           // 0..255
    const int g = tid >> 7, l = tid & 127;
    const int tc = l & 7, trr = l >> 3;    // trr 0..15
    float* Tb    = sm + 4352  + g * 4352;  // 64 x stride 68
    float* vpS   = sm + 13056 + g * 4352;  // 64 x stride 68
    float* qgS   = sm + 21760;             // 512
    float* resS  = sm + 22272;             // 512
    int*   growsS = (int*)(sm + 22784);    // 128
    float* d1S   = sm + 22912;             // 192
    float* d1bS  = sm + 23104;
    float* d2bS  = sm + 23168;
    float* cvecS = sm + 23232;
    float* g2bS  = sm + 23296;             // end 23360 floats = 93440 B
    const int pbase = blockIdx.x * 8;

    // ---- setup ----
    loadWp(Wbuf, d2w, tid);
    if (tid < 192) d1S[tid] = d1w[tid];
    if (tid < 64) { d1bS[tid] = d1b[tid]; d2bS[tid] = d2b[tid]; cvecS[tid] = g_cvec[tid]; g2bS[tid] = g2b[tid]; }
    for (int e = tid; e < 512; e += 256) qgS[e] = g_qg[(pbase + (e >> 6)) * 64 + (e & 63)];

    float rx = 0.f, ry = 0.f, rz = 0.f;
    if (l < 64) {
        const int pi_st = pbase + g * 4 + (l >> 4);
        const int grow_st = ((pi_st >> 13) << 13) | knn[pi_st * 16 + (l & 15)];
        growsS[g * 64 + l] = grow_st;
        rx = xyz[pi_st * 3 + 0] - xyz[grow_st * 3 + 0];
        ry = xyz[pi_st * 3 + 1] - xyz[grow_st * 3 + 1];
        rz = xyz[pi_st * 3 + 2] - xyz[grow_st * 3 + 2];
    }
    __syncthreads();

    // ---- stage T = relu(rel@d1 + d1b) (threads l<64, one row each) ----
    if (l < 64) {
        const int r = l;
#pragma unroll
        for (int c4 = 0; c4 < 16; c4++) {
            float v[4];
#pragma unroll
            for (int u = 0; u < 4; u++) {
                int f = c4 * 4 + u;
                v[u] = fmaxf(fmaf(rx, d1S[f], fmaf(ry, d1S[64 + f], fmaf(rz, d1S[128 + f], d1bS[f]))), 0.f);
            }
            *reinterpret_cast<float4*>(Tb + r * 68 + c4 * 4) = make_float4(v[0], v[1], v[2], v[3]);
        }
    }
    __syncthreads();

    const int tcoff = tc * 8 + ((tc >> 2) << 2);   // padded col offset
    const int c0 = tc * 8;
    unsigned long long acc[4][4];
    float2 u0, u1, u2, u3;

    // ---- GEMM1: pos = T@d2 (+d2b); vp = v_gather + pos -> vpS ----
    gemmT4(Tb, Wbuf, trr, tcoff, acc);
#pragma unroll
    for (int i = 0; i < 4; i++) {
        int r = trr + 16 * i;
        int grow = growsS[g * 64 + r];
        float4 v0 = __ldg(reinterpret_cast<const float4*>(g_v + (size_t)grow * 64 + c0));
        float4 v1 = __ldg(reinterpret_cast<const float4*>(g_v + (size_t)grow * 64 + c0 + 4));
        u0 = unpk(acc[i][0]); u1 = unpk(acc[i][1]); u2 = unpk(acc[i][2]); u3 = unpk(acc[i][3]);
        float4 w0 = make_float4(v0.x + u0.x + d2bS[c0 + 0], v0.y + u0.y + d2bS[c0 + 1],
                                v0.z + u1.x + d2bS[c0 + 2], v0.w + u1.y + d2bS[c0 + 3]);
        float4 w1 = make_float4(v1.x + u2.x + d2bS[c0 + 4], v1.y + u2.y + d2bS[c0 + 5],
                                v1.z + u3.x + d2bS[c0 + 6], v1.w + u3.y + d2bS[c0 + 7]);
        *reinterpret_cast<float4*>(vpS + r * 68 + c0)     = w0;
        *reinterpret_cast<float4*>(vpS + r * 68 + c0 + 4) = w1;
    }
    __syncthreads();                 // GEMM1 Wbuf reads done
    loadWp(Wbuf, (const float*)g_Wd2g1, tid);
    __syncthreads();

    // ---- GEMM2: Tg = T@(d2@g1); a1 = relu(Tg + qg - kg + cvec) ----
    gemmT4(Tb, Wbuf, trr, tcoff, acc);
    float a1s[4][8];
#pragma unroll
    for (int i = 0; i < 4; i++) {
        int r = trr + 16 * i;
        int grow = growsS[g * 64 + r];
        int lp = g * 4 + (r >> 4);
        float4 k0v = __ldg(reinterpret_cast<const float4*>(g_kg + (size_t)grow * 64 + c0));
        float4 k1v = __ldg(reinterpret_cast<const float4*>(g_kg + (size_t)grow * 64 + c0 + 4));
        float4 q0 = *reinterpret_cast<const float4*>(qgS + lp * 64 + c0);
        float4 q1 = *reinterpret_cast<const float4*>(qgS + lp * 64 + c0 + 4);
        u0 = unpk(acc[i][0]); u1 = unpk(acc[i][1]); u2 = unpk(acc[i][2]); u3 = unpk(acc[i][3]);
        a1s[i][0] = fmaxf(u0.x + q0.x - k0v.x + cvecS[c0 + 0], 0.f);
        a1s[i][1] = fmaxf(u0.y + q0.y - k0v.y + cvecS[c0 + 1], 0.f);
        a1s[i][2] = fmaxf(u1.x + q0.z - k0v.z + cvecS[c0 + 2], 0.f);
        a1s[i][3] = fmaxf(u1.y + q0.w - k0v.w + cvecS[c0 + 3], 0.f);
        a1s[i][4] = fmaxf(u2.x + q1.x - k1v.x + cvecS[c0 + 4], 0.f);
        a1s[i][5] = fmaxf(u2.y + q1.y - k1v.y + cvecS[c0 + 5], 0.f);
        a1s[i][6] = fmaxf(u3.x + q1.z - k1v.z + cvecS[c0 + 6], 0.f);
        a1s[i][7] = fmaxf(u3.y + q1.w - k1v.w + cvecS[c0 + 7], 0.f);
    }
    __syncthreads();                 // GEMM2 Tb/Wbuf reads done
#pragma unroll
    for (int i = 0; i < 4; i++) {
        int r = trr + 16 * i;
        *reinterpret_cast<float4*>(Tb + r * 68 + c0)     = make_float4(a1s[i][0], a1s[i][1], a1s[i][2], a1s[i][3]);
        *reinterpret_cast<float4*>(Tb + r * 68 + c0 + 4) = make_float4(a1s[i][4], a1s[i][5], a1s[i][6], a1s[i][7]);
    }
    loadWp(Wbuf, g2w, tid);
    __syncthreads();

    // ---- GEMM3: logits = a1@g2 + g2b ----
    gemmT4(Tb, Wbuf, trr, tcoff, acc);
#pragma unroll
    for (int i = 0; i < 4; i++) {
        u0 = unpk(acc[i][0]); u1 = unpk(acc[i][1]); u2 = unpk(acc[i][2]); u3 = unpk(acc[i][3]);
        a1s[i][0] = u0.x + g2bS[c0 + 0]; a1s[i][1] = u0.y + g2bS[c0 + 1];
        a1s[i][2] = u1.x + g2bS[c0 + 2]; a1s[i][3] = u1.y + g2bS[c0 + 3];
        a1s[i][4] = u2.x + g2bS[c0 + 4]; a1s[i][5] = u2.y + g2bS[c0 + 5];
        a1s[i][6] = u3.x + g2bS[c0 + 6]; a1s[i][7] = u3.y + g2bS[c0 + 7];
    }
    __syncthreads();                 // GEMM3 reads done
#pragma unroll
    for (int i = 0; i < 4; i++) {
        int r = trr + 16 * i;
        *reinterpret_cast<float4*>(Tb + r * 68 + c0)     = make_float4(a1s[i][0], a1s[i][1], a1s[i][2], a1s[i][3]);
        *reinterpret_cast<float4*>(Tb + r * 68 + c0 + 4) = make_float4(a1s[i][4], a1s[i][5], a1s[i][6], a1s[i][7]);
    }
    __syncthreads();

    // ---- softmax over neighbors (axis j) per (point, channel) + res ----
    {
        const int f = l & 63, ph = l >> 6;      // 2 points per thread
#pragma unroll
        for (int it = 0; it < 2; it++) {
            const int p = it * 2 + ph;
            const int pi = pbase + g * 4 + p;
            float z[16], m = -3.402823e38f;
#pragma unroll
            for (int j = 0; j < 16; j++) {
                z[j] = Tb[(p * 16 + j) * 68 + f];
                m = fmaxf(m, z[j]);
            }
            float s = 0.f;
#pragma unroll
            for (int j = 0; j < 16; j++) { float e = __expf((z[j] - m) * 0.125f); z[j] = e; s += e; }
            float inv = 1.f / s, racc = 0.f;
#pragma unroll
            for (int j = 0; j < 16; j++) {
                float a = z[j] * inv;
                outAttn[((size_t)pi * 16 + j) * 64 + f] = a;
                racc = fmaf(a, vpS[(p * 16 + j) * 68 + f], racc);
            }
            resS[(g * 4 + p) * 64 + f] = racc;
        }
    }
    __syncthreads();

    // ---- out = res@fc2 + fc2b + features (2 points per thread) ----
    {
        const int f = l & 63, ph = l >> 6;
        const int p0 = g * 4 + ph * 2;          // two consecutive local points
        float o0 = fc2b[f] + features[(size_t)(pbase + p0 + 0) * 64 + f];
        float o1 = fc2b[f] + features[(size_t)(pbase + p0 + 1) * 64 + f];
#pragma unroll 8
        for (int i = 0; i < 64; i++) {
            float w = __ldg(fc2w + i * 64 + f);
            o0 = fmaf(resS[(p0 + 0) * 64 + i], w, o0);
            o1 = fmaf(resS[(p0 + 1) * 64 + i], w, o1);
        }
        outRes[(size_t)(pbase + p0 + 0) * 64 + f] = o0;
        outRes[(size_t)(pbase + p0 + 1) * 64 + f] = o1;
    }
}

// =========================================================================
extern "C" void kernel_launch(void* const* d_in, const int* in_sizes, int n_in,
                              void* d_out, int out_size) {
    const float* xyz      = (const float*)d_in[0];
    const float* features = (const float*)d_in[1];
    const int*   knn      = (const int*)d_in[2];
    const float* fc1w = (const float*)d_in[3];
    const float* fc1b = (const float*)d_in[4];
    const float* fc2w = (const float*)d_in[5];
    const float* fc2b = (const float*)d_in[6];
    const float* d1w  = (const float*)d_in[7];
    const float* d1b  = (const float*)d_in[8];
    const float* d2w  = (const float*)d_in[9];
    const float* d2b  = (const float*)d_in[10];
    const float* g1w  = (const float*)d_in[11];
    const float* g1b  = (const float*)d_in[12];
    const float* g2w  = (const float*)d_in[13];
    const float* g2b  = (const float*)d_in[14];
    const float* wq   = (const float*)d_in[15];
    const float* wk   = (const float*)d_in[16];
    const float* wv   = (const float*)d_in[17];

    float* outRes  = (float*)d_out;
    float* outAttn = outRes + (size_t)Mm * 64;   // tuple order: (res, attn)

    const int smem2 = 23360 * 4;   // 93440 B -> 2 CTAs/SM
    cudaFuncSetAttribute(k2_main, cudaFuncAttributeMaxDynamicSharedMemorySize, smem2);

    k0_prep<<<3, 256>>>(d2w, g1w, wq, wk, d2b, g1b);
    k1_proj<<<Mm / 64, 256>>>(features, fc1w, fc1b, wv);
    k2_main<<<Mm / 8, 256, smem2>>>(xyz, features, knn,
                                    d1w, d1b, d2w, d2b, g2w, g2b,
                                    fc2w, fc2b, outRes, outAttn);
}

// round 11
// speedup vs baseline: 1.4102x; 1.0166x over previous
#include <cuda_runtime.h>
#include <cstdint>

#define Mm 32768   // B*N points

// ---------------- static device scratch ----------------
__device__ float g_qg[Mm * 64];   // x @ (wq@g1)
__device__ float g_kg[Mm * 64];   // x @ (wk@g1)
__device__ float g_v [Mm * 64];   // x @ wv
__device__ float g_Wd2g1[4096];   // d2 @ g1
__device__ float g_Wqg1[4096];    // wq @ g1
__device__ float g_Wkg1[4096];    // wk @ g1
__device__ float g_cvec[64];      // d2b @ g1 + g1b

// ---------------- f32x2 packed-FMA helpers ----------------
__device__ __forceinline__ unsigned long long pack2(float x, float y) {
    unsigned long long r; asm("mov.b64 %0, {%1, %2};" : "=l"(r) : "f"(x), "f"(y)); return r;
}
__device__ __forceinline__ void fma2(unsigned long long& d, unsigned long long a, unsigned long long b) {
    asm("fma.rn.f32x2 %0, %1, %2, %0;" : "+l"(d) : "l"(a), "l"(b));
}
__device__ __forceinline__ float2 unpk(unsigned long long v) {
    float x, y; asm("mov.b64 {%0, %1}, %2;" : "=f"(x), "=f"(y) : "l"(v)); return make_float2(x, y);
}

// ---------------- 4x4-tile gemm (k0/k1) ----------------
__device__ __forceinline__ void rank1(float a0, float a1, float a2, float a3,
                                      ulonglong2 b, unsigned long long acc[4][2]) {
    unsigned long long t;
    t = pack2(a0, a0); fma2(acc[0][0], t, b.x); fma2(acc[0][1], t, b.y);
    t = pack2(a1, a1); fma2(acc[1][0], t, b.x); fma2(acc[1][1], t, b.y);
    t = pack2(a2, a2); fma2(acc[2][0], t, b.x); fma2(acc[2][1], t, b.y);
    t = pack2(a3, a3); fma2(acc[3][0], t, b.x); fma2(acc[3][1], t, b.y);
}
__device__ __forceinline__ void gemm64(const float* As, const float* Ws,
                                       int r0, int c0, unsigned long long acc[4][2]) {
#pragma unroll
    for (int i = 0; i < 4; i++) { acc[i][0] = 0ULL; acc[i][1] = 0ULL; }
#pragma unroll
    for (int k4 = 0; k4 < 16; ++k4) {
        float4 a0 = *reinterpret_cast<const float4*>(As + (r0 + 0) * 68 + k4 * 4);
        float4 a1 = *reinterpret_cast<const float4*>(As + (r0 + 1) * 68 + k4 * 4);
        float4 a2 = *reinterpret_cast<const float4*>(As + (r0 + 2) * 68 + k4 * 4);
        float4 a3 = *reinterpret_cast<const float4*>(As + (r0 + 3) * 68 + k4 * 4);
        ulonglong2 b0 = *reinterpret_cast<const ulonglong2*>(Ws + (k4 * 4 + 0) * 68 + c0);
        ulonglong2 b1 = *reinterpret_cast<const ulonglong2*>(Ws + (k4 * 4 + 1) * 68 + c0);
        ulonglong2 b2 = *reinterpret_cast<const ulonglong2*>(Ws + (k4 * 4 + 2) * 68 + c0);
        ulonglong2 b3 = *reinterpret_cast<const ulonglong2*>(Ws + (k4 * 4 + 3) * 68 + c0);
        rank1(a0.x, a1.x, a2.x, a3.x, b0, acc);
        rank1(a0.y, a1.y, a2.y, a3.y, b1, acc);
        rank1(a0.z, a1.z, a2.z, a3.z, b2, acc);
        rank1(a0.w, a1.w, a2.w, a3.w, b3, acc);
    }
}
__device__ __forceinline__ void loadW(float* dst, const float* __restrict__ src, int tid) {
#pragma unroll
    for (int e = tid; e < 1024; e += 256) {
        int row = e >> 4, c4 = e & 15;
        float4 v = *reinterpret_cast<const float4*>(src + row * 64 + c4 * 4);
        *reinterpret_cast<float4*>(dst + row * 68 + c4 * 4) = v;
    }
}

// =========================================================================
// k0: weight products (canary kernel — keep identical across rounds)
// =========================================================================
__global__ __launch_bounds__(256)
void k0_prep(const float* __restrict__ d2w, const float* __restrict__ g1w,
             const float* __restrict__ wq, const float* __restrict__ wk,
             const float* __restrict__ d2b, const float* __restrict__ g1b) {
    __shared__ float As[64 * 68];
    __shared__ float Bs[64 * 68];
    const int tid = threadIdx.x, m = blockIdx.x;
    const float* A = (m == 0) ? d2w : (m == 1) ? wq : wk;
    loadW(As, A, tid);
    loadW(Bs, g1w, tid);
    __syncthreads();
    const int r0 = (tid >> 4) * 4, c0 = (tid & 15) * 4;
    unsigned long long acc[4][2];
    gemm64(As, Bs, r0, c0, acc);
    float* dst = (m == 0) ? g_Wd2g1 : (m == 1) ? g_Wqg1 : g_Wkg1;
#pragma unroll
    for (int i = 0; i < 4; i++) {
        float2 u0 = unpk(acc[i][0]), u1 = unpk(acc[i][1]);
        *reinterpret_cast<float4*>(dst + (r0 + i) * 64 + c0) = make_float4(u0.x, u0.y, u1.x, u1.y);
    }
    if (m == 0 && tid < 64) {
        float c = g1b[tid];
#pragma unroll 8
        for (int k = 0; k < 64; k++) c = fmaf(__ldg(&d2b[k]), Bs[k * 68 + tid], c);
        g_cvec[tid] = c;
    }
}

// =========================================================================
// k1: x = features@fc1+b ; qg = x@Wqg1 ; kg = x@Wkg1 ; v = x@wv
// =========================================================================
__global__ __launch_bounds__(256)
void k1_proj(const float* __restrict__ features,
             const float* __restrict__ fc1w, const float* __restrict__ fc1b,
             const float* __restrict__ wv) {
    __shared__ float Fs[64 * 68];
    __shared__ float Ws[64 * 68];
    const int tid = threadIdx.x;
    const int m0 = blockIdx.x * 64;
    const int r0 = (tid >> 4) * 4, c0 = (tid & 15) * 4;

#pragma unroll
    for (int e = tid; e < 1024; e += 256) {
        int row = e >> 4, c4 = e & 15;
        float4 v = *reinterpret_cast<const float4*>(features + (m0 + row) * 64 + c4 * 4);
        *reinterpret_cast<float4*>(Fs + row * 68 + c4 * 4) = v;
    }
    loadW(Ws, fc1w, tid);
    __syncthreads();

    unsigned long long acc[4][2];
    gemm64(Fs, Ws, r0, c0, acc);
    __syncthreads();
#pragma unroll
    for (int i = 0; i < 4; i++) {
        float2 u0 = unpk(acc[i][0]), u1 = unpk(acc[i][1]);
        Fs[(r0 + i) * 68 + c0 + 0] = u0.x + __ldg(&fc1b[c0 + 0]);
        Fs[(r0 + i) * 68 + c0 + 1] = u0.y + __ldg(&fc1b[c0 + 1]);
        Fs[(r0 + i) * 68 + c0 + 2] = u1.x + __ldg(&fc1b[c0 + 2]);
        Fs[(r0 + i) * 68 + c0 + 3] = u1.y + __ldg(&fc1b[c0 + 3]);
    }
    loadW(Ws, (const float*)g_Wqg1, tid);
    __syncthreads();
    gemm64(Fs, Ws, r0, c0, acc);
#pragma unroll
    for (int i = 0; i < 4; i++) {
        float2 u0 = unpk(acc[i][0]), u1 = unpk(acc[i][1]);
        *reinterpret_cast<float4*>(g_qg + (m0 + r0 + i) * 64 + c0) = make_float4(u0.x, u0.y, u1.x, u1.y);
    }
    __syncthreads();
    loadW(Ws, (const float*)g_Wkg1, tid);
    __syncthreads();
    gemm64(Fs, Ws, r0, c0, acc);
#pragma unroll
    for (int i = 0; i < 4; i++) {
        float2 u0 = unpk(acc[i][0]), u1 = unpk(acc[i][1]);
        *reinterpret_cast<float4*>(g_kg + (m0 + r0 + i) * 64 + c0) = make_float4(u0.x, u0.y, u1.x, u1.y);
    }
    __syncthreads();
    loadW(Ws, wv, tid);
    __syncthreads();
    gemm64(Fs, Ws, r0, c0, acc);
#pragma unroll
    for (int i = 0; i < 4; i++) {
        float2 u0 = unpk(acc[i][0]), u1 = unpk(acc[i][1]);
        *reinterpret_cast<float4*>(g_v + (m0 + r0 + i) * 64 + c0) = make_float4(u0.x, u0.y, u1.x, u1.y);
    }
}

// =========================================================================
// k2: 256 thr = 2 groups x 128 thr; group = 64 rows (4 pts x 16 nbrs).
// 4x8 register tiles, 2 CTAs/SM (16 warps). NEW vs R10:
//   - double-buffered weights (W0=d2, W1=d2@g1 at setup; g2 staged through
//     registers during GEMM2) -> no serialized mid-kernel weight stalls
//   - v-gather prefetched into registers before GEMM1
// =========================================================================
__device__ __forceinline__ void gemmT4(const float* __restrict__ Tb,
                                       const float* __restrict__ W,
                                       int trr, int tcoff, unsigned long long acc[4][4]) {
    const float4* ap0 = reinterpret_cast<const float4*>(Tb + (trr +  0) * 68);
    const float4* ap1 = reinterpret_cast<const float4*>(Tb + (trr + 16) * 68);
    const float4* ap2 = reinterpret_cast<const float4*>(Tb + (trr + 32) * 68);
    const float4* ap3 = reinterpret_cast<const float4*>(Tb + (trr + 48) * 68);
    const ulonglong2* wp = reinterpret_cast<const ulonglong2*>(W + tcoff);
#pragma unroll
    for (int i = 0; i < 4; i++) { acc[i][0] = acc[i][1] = acc[i][2] = acc[i][3] = 0ULL; }
#pragma unroll
    for (int k4 = 0; k4 < 16; k4++) {
        float4 Av[4];
        Av[0] = ap0[k4]; Av[1] = ap1[k4]; Av[2] = ap2[k4]; Av[3] = ap3[k4];
#pragma unroll
        for (int kk = 0; kk < 4; kk++) {
            ulonglong2 b0 = wp[(k4 * 4 + kk) * 17];
            ulonglong2 b1 = wp[(k4 * 4 + kk) * 17 + 1];
#pragma unroll
            for (int i = 0; i < 4; i++) {
                float a = (kk == 0) ? Av[i].x : (kk == 1) ? Av[i].y : (kk == 2) ? Av[i].z : Av[i].w;
                unsigned long long t = pack2(a, a);
                fma2(acc[i][0], t, b0.x); fma2(acc[i][1], t, b0.y);
                fma2(acc[i][2], t, b1.x); fma2(acc[i][3], t, b1.y);
            }
        }
    }
}

// cooperative padded weight load (256 threads): col -> col + 4*(col>=32)
__device__ __forceinline__ void loadWp(float* dst, const float* __restrict__ src, int tid) {
#pragma unroll
    for (int e = tid; e < 1024; e += 256) {
        int row = e >> 4, c4 = e & 15;
        float4 v = __ldg(reinterpret_cast<const float4*>(src + row * 64 + c4 * 4));
        *reinterpret_cast<float4*>(dst + row * 68 + c4 * 4 + ((c4 >> 3) << 2)) = v;
    }
}

__global__ __launch_bounds__(256, 2)
void k2_main(const float* __restrict__ xyz, const float* __restrict__ features,
             const int* __restrict__ knn,
             const float* __restrict__ d1w, const float* __restrict__ d1b,
             const float* __restrict__ d2w, const float* __restrict__ d2b,
             const float* __restrict__ g2w, const float* __restrict__ g2b,
             const float* __restrict__ fc2w, const float* __restrict__ fc2b,
             float* __restrict__ outRes, float* __restrict__ outAttn) {
    extern __shared__ float sm[];
    float* W0    = sm;                     // 4352 (padded cols)
    float* W1    = sm + 4352;              // 4352
    const int tid = threadIdx.x;           // 0..255
    const int g = tid >> 7, l = tid & 127;
    const int tc = l & 7, trr = l >> 3;    // trr 0..15
    float* Tb    = sm + 8704  + g * 4352;  // 64 x stride 68
    float* vpS   = sm + 17408 + g * 4352;  // 64 x stride 68
    float* qgS   = sm + 26112;             // 512
    float* resS  = sm + 26624;             // 512
    int*   growsS = (int*)(sm + 27136);    // 128
    float* d1S   = sm + 27264;             // 192
    float* d1bS  = sm + 27456;
    float* d2bS  = sm + 27520;
    float* cvecS = sm + 27584;
    float* g2bS  = sm + 27648;             // end 27712 floats = 110848 B
    const int pbase = blockIdx.x * 8;

    // ---- setup: both weight buffers resident ----
    loadWp(W0, d2w, tid);
    loadWp(W1, (const float*)g_Wd2g1, tid);
    if (tid < 192) d1S[tid] = d1w[tid];
    if (tid < 64) { d1bS[tid] = d1b[tid]; d2bS[tid] = d2b[tid]; cvecS[tid] = g_cvec[tid]; g2bS[tid] = g2b[tid]; }
    for (int e = tid; e < 512; e += 256) qgS[e] = g_qg[(pbase + (e >> 6)) * 64 + (e & 63)];

    float rx = 0.f, ry = 0.f, rz = 0.f;
    if (l < 64) {
        const int pi_st = pbase + g * 4 + (l >> 4);
        const int grow_st = ((pi_st >> 13) << 13) | knn[pi_st * 16 + (l & 15)];
        growsS[g * 64 + l] = grow_st;
        rx = xyz[pi_st * 3 + 0] - xyz[grow_st * 3 + 0];
        ry = xyz[pi_st * 3 + 1] - xyz[grow_st * 3 + 1];
        rz = xyz[pi_st * 3 + 2] - xyz[grow_st * 3 + 2];
    }
    __syncthreads();

    const int c0 = tc * 8;

    // ---- prefetch v-gather into registers (covered by T-stage + GEMM1) ----
    float4 vpre0[4], vpre1[4];
#pragma unroll
    for (int i = 0; i < 4; i++) {
        int grow = growsS[g * 64 + trr + 16 * i];
        vpre0[i] = __ldg(reinterpret_cast<const float4*>(g_v + (size_t)grow * 64 + c0));
        vpre1[i] = __ldg(reinterpret_cast<const float4*>(g_v + (size_t)grow * 64 + c0 + 4));
    }

    // ---- stage T = relu(rel@d1 + d1b) (threads l<64, one row each) ----
    if (l < 64) {
        const int r = l;
#pragma unroll
        for (int c4 = 0; c4 < 16; c4++) {
            float v[4];
#pragma unroll
            for (int u = 0; u < 4; u++) {
                int f = c4 * 4 + u;
                v[u] = fmaxf(fmaf(rx, d1S[f], fmaf(ry, d1S[64 + f], fmaf(rz, d1S[128 + f], d1bS[f]))), 0.f);
            }
            *reinterpret_cast<float4*>(Tb + r * 68 + c4 * 4) = make_float4(v[0], v[1], v[2], v[3]);
        }
    }
    __syncthreads();

    const int tcoff = tc * 8 + ((tc >> 2) << 2);   // padded col offset
    unsigned long long acc[4][4];
    float2 u0, u1, u2, u3;

    // ---- GEMM1: pos = T@d2 (+d2b); vp = v_prefetch + pos -> vpS ----
    gemmT4(Tb, W0, trr, tcoff, acc);
#pragma unroll
    for (int i = 0; i < 4; i++) {
        int r = trr + 16 * i;
        u0 = unpk(acc[i][0]); u1 = unpk(acc[i][1]); u2 = unpk(acc[i][2]); u3 = unpk(acc[i][3]);
        float4 w0 = make_float4(vpre0[i].x + u0.x + d2bS[c0 + 0], vpre0[i].y + u0.y + d2bS[c0 + 1],
                                vpre0[i].z + u1.x + d2bS[c0 + 2], vpre0[i].w + u1.y + d2bS[c0 + 3]);
        float4 w1 = make_float4(vpre1[i].x + u2.x + d2bS[c0 + 4], vpre1[i].y + u2.y + d2bS[c0 + 5],
                                vpre1[i].z + u3.x + d2bS[c0 + 6], vpre1[i].w + u3.y + d2bS[c0 + 7]);
        *reinterpret_cast<float4*>(vpS + r * 68 + c0)     = w0;
        *reinterpret_cast<float4*>(vpS + r * 68 + c0 + 4) = w1;
    }
    __syncthreads();                 // GEMM1 W0/Tb reads done

    // ---- stage g2 into registers (L2 latency rides under GEMM2) ----
    float4 g2r[4];
#pragma unroll
    for (int e2 = 0; e2 < 4; e2++) {
        int e = tid + e2 * 256;
        int row = e >> 4, c4 = e & 15;
        g2r[e2] = __ldg(reinterpret_cast<const float4*>(g2w + row * 64 + c4 * 4));
    }

    // ---- GEMM2: Tg = T@(d2@g1); a1 = relu(Tg + qg - kg + cvec) ----
    gemmT4(Tb, W1, trr, tcoff, acc);
    float a1s[4][8];
#pragma unroll
    for (int i = 0; i < 4; i++) {
        int r = trr + 16 * i;
        int grow = growsS[g * 64 + r];
        int lp = g * 4 + (r >> 4);
        float4 k0v = __ldg(reinterpret_cast<const float4*>(g_kg + (size_t)grow * 64 + c0));
        float4 k1v = __ldg(reinterpret_cast<const float4*>(g_kg + (size_t)grow * 64 + c0 + 4));
        float4 q0 = *reinterpret_cast<const float4*>(qgS + lp * 64 + c0);
        float4 q1 = *reinterpret_cast<const float4*>(qgS + lp * 64 + c0 + 4);
        u0 = unpk(acc[i][0]); u1 = unpk(acc[i][1]); u2 = unpk(acc[i][2]); u3 = unpk(acc[i][3]);
        a1s[i][0] = fmaxf(u0.x + q0.x - k0v.x + cvecS[c0 + 0], 0.f);
        a1s[i][1] = fmaxf(u0.y + q0.y - k0v.y + cvecS[c0 + 1], 0.f);
        a1s[i][2] = fmaxf(u1.x + q0.z - k0v.z + cvecS[c0 + 2], 0.f);
        a1s[i][3] = fmaxf(u1.y + q0.w - k0v.w + cvecS[c0 + 3], 0.f);
        a1s[i][4] = fmaxf(u2.x + q1.x - k1v.x + cvecS[c0 + 4], 0.f);
        a1s[i][5] = fmaxf(u2.y + q1.y - k1v.y + cvecS[c0 + 5], 0.f);
        a1s[i][6] = fmaxf(u3.x + q1.z - k1v.z + cvecS[c0 + 6], 0.f);
        a1s[i][7] = fmaxf(u3.y + q1.w - k1v.w + cvecS[c0 + 7], 0.f);
    }
    __syncthreads();                 // GEMM2 Tb/W1 reads done (and GEMM1 W0 readers long gone)
    // write a1 -> Tb ; store staged g2 -> W0
#pragma unroll
    for (int i = 0; i < 4; i++) {
        int r = trr + 16 * i;
        *reinterpret_cast<float4*>(Tb + r * 68 + c0)     = make_float4(a1s[i][0], a1s[i][1], a1s[i][2], a1s[i][3]);
        *reinterpret_cast<float4*>(Tb + r * 68 + c0 + 4) = make_float4(a1s[i][4], a1s[i][5], a1s[i][6], a1s[i][7]);
    }
#pragma unroll
    for (int e2 = 0; e2 < 4; e2++) {
        int e = tid + e2 * 256;
        int row = e >> 4, c4 = e & 15;
        *reinterpret_cast<float4*>(W0 + row * 68 + c4 * 4 + ((c4 >> 3) << 2)) = g2r[e2];
    }
    __syncthreads();

    // ---- GEMM3: logits = a1@g2 + g2b ----
    gemmT4(Tb, W0, trr, tcoff, acc);
#pragma unroll
    for (int i = 0; i < 4; i++) {
        u0 = unpk(acc[i][0]); u1 = unpk(acc[i][1]); u2 = unpk(acc[i][2]); u3 = unpk(acc[i][3]);
        a1s[i][0] = u0.x + g2bS[c0 + 0]; a1s[i][1] = u0.y + g2bS[c0 + 1];
        a1s[i][2] = u1.x + g2bS[c0 + 2]; a1s[i][3] = u1.y + g2bS[c0 + 3];
        a1s[i][4] = u2.x + g2bS[c0 + 4]; a1s[i][5] = u2.y + g2bS[c0 + 5];
        a1s[i][6] = u3.x + g2bS[c0 + 6]; a1s[i][7] = u3.y + g2bS[c0 + 7];
    }
    __syncthreads();                 // GEMM3 reads done
#pragma unroll
    for (int i = 0; i < 4; i++) {
        int r = trr + 16 * i;
        *reinterpret_cast<float4*>(Tb + r * 68 + c0)     = make_float4(a1s[i][0], a1s[i][1], a1s[i][2], a1s[i][3]);
        *reinterpret_cast<float4*>(Tb + r * 68 + c0 + 4) = make_float4(a1s[i][4], a1s[i][5], a1s[i][6], a1s[i][7]);
    }
    __syncthreads();

    // ---- softmax over neighbors (axis j) per (point, channel) + res ----
    {
        const int f = l & 63, ph = l >> 6;      // 2 points per thread
#pragma unroll
        for (int it = 0; it < 2; it++) {
            const int p = it * 2 + ph;
            const int pi = pbase + g * 4 + p;
            float z[16], m = -3.402823e38f;
#pragma unroll
            for (int j = 0; j < 16; j++) {
                z[j] = Tb[(p * 16 + j) * 68 + f];
                m = fmaxf(m, z[j]);
            }
            float s = 0.f;
#pragma unroll
            for (int j = 0; j < 16; j++) { float e = __expf((z[j] - m) * 0.125f); z[j] = e; s += e; }
            float inv = 1.f / s, racc = 0.f;
#pragma unroll
            for (int j = 0; j < 16; j++) {
                float a = z[j] * inv;
                outAttn[((size_t)pi * 16 + j) * 64 + f] = a;
                racc = fmaf(a, vpS[(p * 16 + j) * 68 + f], racc);
            }
            resS[(g * 4 + p) * 64 + f] = racc;
        }
    }
    __syncthreads();

    // ---- out = res@fc2 + fc2b + features (2 points per thread) ----
    {
        const int f = l & 63, ph = l >> 6;
        const int p0 = g * 4 + ph * 2;          // two consecutive local points
        float o0 = fc2b[f] + features[(size_t)(pbase + p0 + 0) * 64 + f];
        float o1 = fc2b[f] + features[(size_t)(pbase + p0 + 1) * 64 + f];
#pragma unroll 8
        for (int i = 0; i < 64; i++) {
            float w = __ldg(fc2w + i * 64 + f);
            o0 = fmaf(resS[(p0 + 0) * 64 + i], w, o0);
            o1 = fmaf(resS[(p0 + 1) * 64 + i], w, o1);
        }
        outRes[(size_t)(pbase + p0 + 0) * 64 + f] = o0;
        outRes[(size_t)(pbase + p0 + 1) * 64 + f] = o1;
    }
}

// =========================================================================
extern "C" void kernel_launch(void* const* d_in, const int* in_sizes, int n_in,
                              void* d_out, int out_size) {
    const float* xyz      = (const float*)d_in[0];
    const float* features = (const float*)d_in[1];
    const int*   knn      = (const int*)d_in[2];
    const float* fc1w = (const float*)d_in[3];
    const float* fc1b = (const float*)d_in[4];
    const float* fc2w = (const float*)d_in[5];
    const float* fc2b = (const float*)d_in[6];
    const float* d1w  = (const float*)d_in[7];
    const float* d1b  = (const float*)d_in[8];
    const float* d2w  = (const float*)d_in[9];
    const float* d2b  = (const float*)d_in[10];
    const float* g1w  = (const float*)d_in[11];
    const float* g1b  = (const float*)d_in[12];
    const float* g2w  = (const float*)d_in[13];
    const float* g2b  = (const float*)d_in[14];
    const float* wq   = (const float*)d_in[15];
    const float* wk   = (const float*)d_in[16];
    const float* wv   = (const float*)d_in[17];

    float* outRes  = (float*)d_out;
    float* outAttn = outRes + (size_t)Mm * 64;   // tuple order: (res, attn)

    const int smem2 = 27712 * 4;   // 110848 B -> still 2 CTAs/SM
    cudaFuncSetAttribute(k2_main, cudaFuncAttributeMaxDynamicSharedMemorySize, smem2);

    k0_prep<<<3, 256>>>(d2w, g1w, wq, wk, d2b, g1b);
    k1_proj<<<Mm / 64, 256>>>(features, fc1w, fc1b, wv);
    k2_main<<<Mm / 8, 256, smem2>>>(xyz, features, knn,
                                    d1w, d1b, d2w, d2b, g2w, g2b,
                                    fc2w, fc2b, outRes, outAttn);
}